// round 15
// baseline (speedup 1.0000x reference)
#include <cuda_runtime.h>
#include <cuda_bf16.h>
#include <cstdint>

// ============================================================================
// Problem constants
// ============================================================================
#define HEAD_DIM   128
#define NUM_HEADS  2
#define KWIN       32
#define KD         4096            // KWIN * HEAD_DIM
#define RESCALE    0.015625f       // (32*128)^-0.5

#define MT      32                 // M tile rows ((w,h) pairs) -> 16 windows
#define WTILE   16                 // windows per block
#define NT      32                 // gate outputs per head
#define KCHUNK  128                // K chunk = one full token-head row
#define NITER   (KD / KCHUNK)      // 32

#define NCOPY   192                // copy blocks appended to the fused grid
#define CROWS_PER_CB 224           // rows per copy block (multiple of 32)
#define MAXROWS 65536

// ============================================================================
// Scratch: dest bitmap (zero-initialized; copy blocks self-clean every launch)
// ============================================================================
__device__ uint32_t g_bm[MAXROWS / 32];

// ============================================================================
// Helpers
// ============================================================================
__device__ __forceinline__ uint32_t smem_u32(const void* p) {
    uint32_t a;
    asm("{ .reg .u64 t; cvta.to.shared.u64 t, %1; cvt.u32.u64 %0, t; }"
        : "=r"(a) : "l"(p));
    return a;
}

__device__ __forceinline__ void sts64(uint32_t addr, uint2 v) {
    asm volatile("st.shared.v2.b32 [%0], {%1, %2};"
                 :: "r"(addr), "r"(v.x), "r"(v.y) : "memory");
}

__device__ __forceinline__ uint2 pack_bf16x4(float4 f) {
    __nv_bfloat162 lo = __floats2bfloat162_rn(f.x, f.y);
    __nv_bfloat162 hi = __floats2bfloat162_rn(f.z, f.w);
    uint2 r;
    r.x = *reinterpret_cast<uint32_t*>(&lo);
    r.y = *reinterpret_cast<uint32_t*>(&hi);
    return r;
}

__device__ __forceinline__ void ldmatrix_x4(uint32_t* r, uint32_t addr) {
    asm volatile("ldmatrix.sync.aligned.m8n8.x4.shared.b16 {%0,%1,%2,%3}, [%4];"
                 : "=r"(r[0]), "=r"(r[1]), "=r"(r[2]), "=r"(r[3])
                 : "r"(addr));
}

__device__ __forceinline__ void mma_bf16(float* d, const uint32_t* a,
                                         uint32_t b0, uint32_t b1) {
    asm volatile(
        "mma.sync.aligned.m16n8k16.row.col.f32.bf16.bf16.f32 "
        "{%0,%1,%2,%3}, {%4,%5,%6,%7}, {%8,%9}, {%0,%1,%2,%3};"
        : "+f"(d[0]), "+f"(d[1]), "+f"(d[2]), "+f"(d[3])
        : "r"(a[0]), "r"(a[1]), "r"(a[2]), "r"(a[3]), "r"(b0), "r"(b1));
}

__device__ __forceinline__ float sigf(float x) {
    return 1.0f / (1.0f + __expf(-x * RESCALE));
}

// ============================================================================
// Tiny pre-kernel: dest bitmap set only (gw conversion is in-kernel)
// ============================================================================
__global__ void set_bm_kernel(const int* __restrict__ dest, int W) {
    int i = blockIdx.x * blockDim.x + threadIdx.x;
    if (i < W) {
        int d = dest[i];
        atomicOr(&g_bm[d >> 5], 1u << (d & 31));
    }
}

// ============================================================================
// Fused kernel.
//   GEMM blocks: MT=32, 256 threads, 8 warps = 2(m16) x 2(n16) x 2(k-half).
//     Double-buffered bf16 smem; warp kh computes chunks with (it&1)==kh;
//     partial logits summed across k-half warps in smem, then sigmoid,
//     gated reduction, scatter.
//   Copy blocks: bitmap-masked copy of cbuf -> out + bitmap self-clean.
// ============================================================================
struct SmemT {
    __align__(256) __nv_bfloat16 A[2][MT * KCHUNK];   // 2 x 8 KB
    __align__(256) __nv_bfloat16 B[2][NT * KCHUNK];   // 2 x 8 KB
    int   widx[WTILE * KWIN];                         //  2 KB
    float g[MT * NT];                                 //  4 KB
    int   dst[WTILE];
};

__global__ __launch_bounds__(256, 3)
void fused_kernel(const float* __restrict__ buffer,
                  const float* __restrict__ cbuf,
                  const float* __restrict__ gw,
                  const int*   __restrict__ widx,
                  const int*   __restrict__ dest,
                  float*       __restrict__ out,
                  int W, int Mtot, int nblk, int crows)
{
    __shared__ SmemT sm;
    const int tid = threadIdx.x;

    // ---------------- copy blocks ----------------
    if (blockIdx.x >= (unsigned)nblk) {
        int cb = blockIdx.x - nblk;
        int r0 = cb * CROWS_PER_CB;
        int r1 = min(r0 + CROWS_PER_CB, crows);
        const float4* src4 = reinterpret_cast<const float4*>(cbuf);
        float4*       dst4 = reinterpret_cast<float4*>(out);
        int rsub = tid >> 6;
        int lane = tid & 63;
        for (int r = r0 + rsub; r < r1; r += 4) {
            if ((g_bm[r >> 5] >> (r & 31)) & 1u) continue;   // dest row: skip
            dst4[(size_t)r * 64 + lane] = src4[(size_t)r * 64 + lane];
        }
        // self-clean the block-owned, word-aligned bitmap slice
        __syncthreads();
        if (r0 < crows) {
            int w0 = r0 >> 5;
            int w1 = (min(r0 + CROWS_PER_CB, MAXROWS) + 31) >> 5;
            for (int w = w0 + tid; w < w1; w += 256) g_bm[w] = 0u;
        }
        return;
    }

    // ---------------- GEMM blocks ----------------
    const int warp = tid >> 5;
    const int lid  = tid & 31;
    const int kh   = warp & 1;                         // k-half
    const int nh   = (warp >> 1) & 1;                  // n16 half
    const int mh   = warp >> 2;                        // m16 half

    const int m_base = blockIdx.x * MT;
    const int w_base = blockIdx.x * WTILE;

    // stage window indices + dest slots
    #pragma unroll
    for (int rep = 0; rep < 2; rep++) {
        int t  = rep * 256 + tid;                      // 512 entries
        int wl = t >> 5;
        int wg = w_base + wl;
        sm.widx[t] = (wg < W) ? widx[(size_t)wg * KWIN + (t & 31)] : 0;
    }
    if (tid < WTILE) {
        int wg = w_base + tid;
        sm.dst[tid] = (wg < W) ? dest[wg] : 0;
    }
    __syncthreads();

    // per-thread staging: A 1024 f4 tasks -> 4/thr; B 1024 f4 tasks -> 4/thr
    float4 ra[4];
    float4 rb[4];

    auto load_chunk = [&](int it) {
        #pragma unroll
        for (int rep = 0; rep < 4; rep++) {
            int task = rep * 256 + tid;
            int row  = task >> 5;                      // 0..31
            int c4   = task & 31;
            int m    = m_base + row;
            if (m < Mtot) {
                int slot = sm.widx[(row >> 1) * KWIN + it];
                ra[rep] = *reinterpret_cast<const float4*>(
                    buffer + ((size_t)slot * (NUM_HEADS * HEAD_DIM)
                              + (row & 1) * HEAD_DIM + c4 * 4));
            } else {
                ra[rep] = make_float4(0.f, 0.f, 0.f, 0.f);
            }
        }
        #pragma unroll
        for (int rep = 0; rep < 4; rep++) {
            int task = rep * 256 + tid;
            int row  = task >> 5;                      // 0..31
            int c4   = task & 31;
            rb[rep] = *reinterpret_cast<const float4*>(
                gw + ((size_t)row * KD + it * KCHUNK + c4 * 4));
        }
    };

    auto store_chunk = [&](int s) {
        uint32_t A_base = smem_u32(sm.A[s]);
        uint32_t B_base = smem_u32(sm.B[s]);
        #pragma unroll
        for (int rep = 0; rep < 4; rep++) {
            int task = rep * 256 + tid;
            int row  = task >> 5;
            int c4   = task & 31;
            uint32_t ch = ((uint32_t)(c4 >> 1)) ^ (uint32_t)(row & 7);
            sts64(A_base + row * 256 + ch * 16 + (c4 & 1) * 8, pack_bf16x4(ra[rep]));
        }
        #pragma unroll
        for (int rep = 0; rep < 4; rep++) {
            int task = rep * 256 + tid;
            int row  = task >> 5;
            int c4   = task & 31;
            uint32_t ch = ((uint32_t)(c4 >> 1)) ^ (uint32_t)(row & 7);
            sts64(B_base + row * 256 + ch * 16 + (c4 & 1) * 8, pack_bf16x4(rb[rep]));
        }
    };

    // per-warp MMA geometry (m16 x n16, R4-proven fragment mapping)
    const int wm = mh * 16;
    const int nb = nh * 16;
    const int g  = lid >> 3;
    const int r  = lid & 7;

    const int rowA = wm + ((g & 1) << 3) + r;
    const int cA   = g >> 1;
    const uint32_t xA = (uint32_t)(rowA & 7);
    const int nB   = nb + ((g >> 1) << 3) + r;
    const int cB   = g & 1;
    const uint32_t xB = (uint32_t)(nB & 7);

    float acc[2][4] = {};

    // pipeline: buffers 0,1 pre-filled; regs hold chunk it+2 at iter start
    load_chunk(0); store_chunk(0);
    load_chunk(1); store_chunk(1);
    load_chunk(2);
    __syncthreads();

    for (int it = 0; it < NITER; it++) {
        int s = it & 1;
        if (kh == s) {
            uint32_t baseA = smem_u32(sm.A[s]);
            uint32_t baseB = smem_u32(sm.B[s]);
            #pragma unroll
            for (int ks = 0; ks < 8; ks++) {
                uint32_t a[4], b[4];
                uint32_t chA = ((uint32_t)(ks * 2 + cA)) ^ xA;
                uint32_t chB = ((uint32_t)(ks * 2 + cB)) ^ xB;
                ldmatrix_x4(a, baseA + rowA * 256 + chA * 16);
                ldmatrix_x4(b, baseB + nB   * 256 + chB * 16);
                mma_bf16(acc[0], a, b[0], b[1]);
                mma_bf16(acc[1], a, b[2], b[3]);
            }
        }
        __syncthreads();                               // buffer s free
        if (it + 2 < NITER) store_chunk(s);            // regs hold chunk it+2
        if (it + 3 < NITER) load_chunk(it + 3);        // guarded (was the OOB)
    }

    // combine k-half partials + sigmoid -> smem gates
    {
        int row0 = wm + (lid >> 2);
        int row1 = row0 + 8;
        if (kh == 0) {
            #pragma unroll
            for (int j = 0; j < 2; j++) {
                int n0 = nb + j * 8 + (lid & 3) * 2;
                sm.g[row0 * NT + n0]     = acc[j][0];
                sm.g[row0 * NT + n0 + 1] = acc[j][1];
                sm.g[row1 * NT + n0]     = acc[j][2];
                sm.g[row1 * NT + n0 + 1] = acc[j][3];
            }
        }
        __syncthreads();
        if (kh == 1) {
            #pragma unroll
            for (int j = 0; j < 2; j++) {
                int n0 = nb + j * 8 + (lid & 3) * 2;
                sm.g[row0 * NT + n0]     = sigf(sm.g[row0 * NT + n0]     + acc[j][0]);
                sm.g[row0 * NT + n0 + 1] = sigf(sm.g[row0 * NT + n0 + 1] + acc[j][1]);
                sm.g[row1 * NT + n0]     = sigf(sm.g[row1 * NT + n0]     + acc[j][2]);
                sm.g[row1 * NT + n0 + 1] = sigf(sm.g[row1 * NT + n0 + 1] + acc[j][3]);
            }
        }
    }
    __syncthreads();

    // gated reduction + scatter (tokens L2-hot)
    // 256 threads = 4 windows x 2 heads x 32 float4-lanes; 4 passes.
    const int wsub = tid >> 6;
    const int h    = (tid >> 5) & 1;
    const int dq   = tid & 31;

    for (int p = 0; p < 4; p++) {
        int wl = p * 4 + wsub;
        int wg = w_base + wl;
        if (wg >= W) continue;
        const float* gp = sm.g + (wl * 2 + h) * NT;
        const int*   sp = sm.widx + wl * KWIN;
        float4 acc4 = make_float4(0.f, 0.f, 0.f, 0.f);
        #pragma unroll 8
        for (int k = 0; k < KWIN; k++) {
            float gk = gp[k];
            const float4 t4 = *reinterpret_cast<const float4*>(
                buffer + ((size_t)sp[k] * (NUM_HEADS * HEAD_DIM)
                          + h * HEAD_DIM + dq * 4));
            acc4.x += gk * t4.x;
            acc4.y += gk * t4.y;
            acc4.z += gk * t4.z;
            acc4.w += gk * t4.w;
        }
        *reinterpret_cast<float4*>(
            out + ((size_t)sm.dst[wl] * (NUM_HEADS * HEAD_DIM)
                   + h * HEAD_DIM + dq * 4)) = acc4;
    }
}

// ============================================================================
// Launch
// ============================================================================
extern "C" void kernel_launch(void* const* d_in, const int* in_sizes, int n_in,
                              void* d_out, int out_size)
{
    const float* buffer = (const float*)d_in[0];
    const float* cbuf   = (const float*)d_in[1];
    const float* gw     = (const float*)d_in[2];
    const int*   widx   = (const int*)d_in[3];
    const int*   dest   = (const int*)d_in[4];
    int W     = in_sizes[4];
    int crows = out_size / (NUM_HEADS * HEAD_DIM);

    // tiny pre-kernel: dest bitmap only
    if (W > 0) set_bm_kernel<<<(W + 255) / 256, 256>>>(dest, W);

    int Mtot = 2 * W;
    int nblk = (Mtot + MT - 1) / MT;          // GEMM blocks (0 allowed)
    fused_kernel<<<nblk + NCOPY, 256>>>(
        buffer, cbuf, gw, widx, dest, (float*)d_out, W, Mtot, nblk, crows);
}

// round 16
// speedup vs baseline: 1.1250x; 1.1250x over previous
#include <cuda_runtime.h>
#include <cuda_bf16.h>
#include <cstdint>

// ============================================================================
// Problem constants
// ============================================================================
#define HEAD_DIM   128
#define NUM_HEADS  2
#define KWIN       32
#define KD         4096            // KWIN * HEAD_DIM
#define RESCALE    0.015625f       // (32*128)^-0.5

#define MT      64                 // M tile rows ((w,h) pairs) -> 32 windows
#define WTILE   32                 // windows per block
#define NT      32                 // gate outputs per head
#define KCHUNK  128                // K chunk = one full token-head row
#define NITER   (KD / KCHUNK)      // 32

#define NCOPY   192                // copy blocks appended to the fused grid
#define CROWS_PER_CB 224           // rows per copy block (multiple of 32)
#define MAXROWS 65536

// ============================================================================
// Scratch (__device__ globals; allocation-free rule).
// g_bm is zero-initialized at load; copy blocks self-clean it every launch.
// ============================================================================
__device__ __nv_bfloat16 g_gw[NT * KD];            // 256 KB bf16 gate weight
__device__ uint32_t      g_bm[MAXROWS / 32];       // dest-row bitmap

// ============================================================================
// Helpers
// ============================================================================
__device__ __forceinline__ uint32_t smem_u32(const void* p) {
    uint32_t a;
    asm("{ .reg .u64 t; cvta.to.shared.u64 t, %1; cvt.u32.u64 %0, t; }"
        : "=r"(a) : "l"(p));
    return a;
}

__device__ __forceinline__ void sts64(uint32_t addr, uint2 v) {
    asm volatile("st.shared.v2.b32 [%0], {%1, %2};"
                 :: "r"(addr), "r"(v.x), "r"(v.y) : "memory");
}

__device__ __forceinline__ void sts128(uint32_t addr, uint4 v) {
    asm volatile("st.shared.v4.b32 [%0], {%1, %2, %3, %4};"
                 :: "r"(addr), "r"(v.x), "r"(v.y), "r"(v.z), "r"(v.w) : "memory");
}

__device__ __forceinline__ uint2 pack_bf16x4(float4 f) {
    __nv_bfloat162 lo = __floats2bfloat162_rn(f.x, f.y);
    __nv_bfloat162 hi = __floats2bfloat162_rn(f.z, f.w);
    uint2 r;
    r.x = *reinterpret_cast<uint32_t*>(&lo);
    r.y = *reinterpret_cast<uint32_t*>(&hi);
    return r;
}

__device__ __forceinline__ void ldmatrix_x4(uint32_t* r, uint32_t addr) {
    asm volatile("ldmatrix.sync.aligned.m8n8.x4.shared.b16 {%0,%1,%2,%3}, [%4];"
                 : "=r"(r[0]), "=r"(r[1]), "=r"(r[2]), "=r"(r[3])
                 : "r"(addr));
}

__device__ __forceinline__ void mma_bf16(float* d, const uint32_t* a,
                                         uint32_t b0, uint32_t b1) {
    asm volatile(
        "mma.sync.aligned.m16n8k16.row.col.f32.bf16.bf16.f32 "
        "{%0,%1,%2,%3}, {%4,%5,%6,%7}, {%8,%9}, {%0,%1,%2,%3};"
        : "+f"(d[0]), "+f"(d[1]), "+f"(d[2]), "+f"(d[3])
        : "r"(a[0]), "r"(a[1]), "r"(a[2]), "r"(a[3]), "r"(b0), "r"(b1));
}

__device__ __forceinline__ float sigf(float x) {
    return 1.0f / (1.0f + __expf(-x * RESCALE));
}

// ============================================================================
// Single pre-kernel: gw fp32 -> bf16 scratch AND dest bitmap set.
// 128 blocks x 256 threads = 32768 threads; W <= 8176 < 32768.
// ============================================================================
__global__ void prep_kernel(const float* __restrict__ gw,
                            const int*   __restrict__ dest, int W) {
    int i = blockIdx.x * blockDim.x + threadIdx.x;     // 32768 float4 tasks
    float4 v = reinterpret_cast<const float4*>(gw)[i];
    reinterpret_cast<uint2*>(g_gw)[i] = pack_bf16x4(v);
    if (i < W) {
        int d = dest[i];
        atomicOr(&g_bm[d >> 5], 1u << (d & 31));
    }
}

// ============================================================================
// Fused kernel (R12 GEMM verbatim; single-use traffic uses streaming hints
// so the copy/output streams do not evict the gather working set from L2).
//   Blocks [0, nblk): gather -> bf16 GEMM -> sigmoid -> gated reduction ->
//     scatter. Double-buffered smem, register-staged next chunk.
//   Blocks [nblk, nblk+NCOPY): bitmap-masked copy of cbuf -> out (ldcs/stcs),
//     then clear own (word-aligned, block-owned) bitmap slice.
// ============================================================================
struct SmemT {
    __align__(256) __nv_bfloat16 A[2][MT * KCHUNK];   // 2 x 16 KB
    __align__(256) __nv_bfloat16 B[2][NT * KCHUNK];   // 2 x  8 KB
    int   widx[WTILE * KWIN];                         //  4 KB
    float g[MT * NT];                                 //  8 KB
    int   dst[WTILE];
};
#define SMEM_BYTES ((int)sizeof(SmemT))

__global__ __launch_bounds__(256, 2)
void fused_kernel(const float* __restrict__ buffer,
                  const float* __restrict__ cbuf,
                  const int*   __restrict__ widx,
                  const int*   __restrict__ dest,
                  float*       __restrict__ out,
                  int W, int Mtot, int nblk, int crows)
{
    extern __shared__ char smraw[];
    SmemT& sm = *reinterpret_cast<SmemT*>(smraw);

    const int tid = threadIdx.x;

    // ---------------- copy blocks ----------------
    if (blockIdx.x >= (unsigned)nblk) {
        int cb = blockIdx.x - nblk;
        int r0 = cb * CROWS_PER_CB;
        int r1 = min(r0 + CROWS_PER_CB, crows);
        const float4* src4 = reinterpret_cast<const float4*>(cbuf);
        float4*       dst4 = reinterpret_cast<float4*>(out);
        int rsub = tid >> 6;
        int lane = tid & 63;
        for (int r = r0 + rsub; r < r1; r += 4) {
            if ((g_bm[r >> 5] >> (r & 31)) & 1u) continue;   // dest row: skip
            float4 v = __ldcs(src4 + (size_t)r * 64 + lane); // streaming read
            __stcs(dst4 + (size_t)r * 64 + lane, v);         // streaming write
        }
        // self-clean the block-owned, word-aligned bitmap slice
        __syncthreads();
        if (r0 < crows) {
            int w0 = r0 >> 5;
            int w1 = (min(r0 + CROWS_PER_CB, MAXROWS) + 31) >> 5;
            for (int w = w0 + tid; w < w1; w += 256) g_bm[w] = 0u;
        }
        return;
    }

    // ---------------- GEMM blocks ----------------
    const int warp = tid >> 5;
    const int lid  = tid & 31;

    const int m_base = blockIdx.x * MT;
    const int w_base = blockIdx.x * WTILE;

    // stage window indices + dest slots
    #pragma unroll
    for (int rep = 0; rep < 4; rep++) {
        int t  = rep * 256 + tid;                      // 1024 entries
        int wl = t >> 5;
        int wg = w_base + wl;
        sm.widx[t] = (wg < W) ? widx[(size_t)wg * KWIN + (t & 31)] : 0;
    }
    if (tid < WTILE) {
        int wg = w_base + tid;
        sm.dst[tid] = (wg < W) ? dest[wg] : 0;
    }
    __syncthreads();

    // per-thread loader tasks: A 2048 float4 -> 8/thr; B 512 uint4 -> 2/thr
    float4 ra[8];
    uint4  rbb[2];

    auto load_chunk = [&](int it) {
        #pragma unroll
        for (int rep = 0; rep < 8; rep++) {
            int task = rep * 256 + tid;
            int row  = task >> 5;
            int c4   = task & 31;
            int m    = m_base + row;
            if (m < Mtot) {
                int slot = sm.widx[(row >> 1) * KWIN + it];
                ra[rep] = *reinterpret_cast<const float4*>(
                    buffer + ((size_t)slot * (NUM_HEADS * HEAD_DIM)
                              + (row & 1) * HEAD_DIM + c4 * 4));
            } else {
                ra[rep] = make_float4(0.f, 0.f, 0.f, 0.f);
            }
        }
        #pragma unroll
        for (int rep = 0; rep < 2; rep++) {
            int task = rep * 256 + tid;                // 512 tasks
            int row  = task >> 4;                      // 0..31
            int c16  = task & 15;                      // 16B chunk (8 bf16)
            rbb[rep] = *reinterpret_cast<const uint4*>(
                g_gw + (size_t)row * KD + it * KCHUNK + c16 * 8);
        }
    };

    auto store_chunk = [&](int s) {
        uint32_t A_base = smem_u32(sm.A[s]);
        uint32_t B_base = smem_u32(sm.B[s]);
        #pragma unroll
        for (int rep = 0; rep < 8; rep++) {
            int task = rep * 256 + tid;
            int row  = task >> 5;
            int c4   = task & 31;
            uint32_t ch = ((uint32_t)(c4 >> 1)) ^ (uint32_t)(row & 7);
            sts64(A_base + row * 256 + ch * 16 + (c4 & 1) * 8, pack_bf16x4(ra[rep]));
        }
        #pragma unroll
        for (int rep = 0; rep < 2; rep++) {
            int task = rep * 256 + tid;
            int row  = task >> 4;
            int c16  = task & 15;
            uint32_t ch = ((uint32_t)c16) ^ (uint32_t)(row & 7);
            sts128(B_base + row * 256 + ch * 16, rbb[rep]);
        }
    };

    // per-warp MMA geometry (warp: M rows (warp>>1)*16, N base (warp&1)*16)
    const int wm = (warp >> 1) * 16;
    const int nb = (warp & 1) * 16;
    const int g  = lid >> 3;
    const int r  = lid & 7;

    const int rowA = wm + ((g & 1) << 3) + r;
    const int cA   = g >> 1;
    const uint32_t xA = (uint32_t)(rowA & 7);
    const int nB   = nb + ((g >> 1) << 3) + r;
    const int cB   = g & 1;
    const uint32_t xB = (uint32_t)(nB & 7);

    float acc[2][4] = {};

    // mainloop: double-buffered smem, one sync per iter
    load_chunk(0);
    store_chunk(0);
    load_chunk(1);
    __syncthreads();

    for (int it = 0; it < NITER; it++) {
        int s = it & 1;
        if (it + 1 < NITER) store_chunk(s ^ 1);        // regs hold chunk it+1
        if (it + 2 < NITER) load_chunk(it + 2);

        uint32_t baseA = smem_u32(sm.A[s]);
        uint32_t baseB = smem_u32(sm.B[s]);
        #pragma unroll
        for (int ks = 0; ks < 8; ks++) {
            uint32_t a[4], b[4];
            uint32_t chA = ((uint32_t)(ks * 2 + cA)) ^ xA;
            uint32_t chB = ((uint32_t)(ks * 2 + cB)) ^ xB;
            ldmatrix_x4(a, baseA + rowA * 256 + chA * 16);
            ldmatrix_x4(b, baseB + nB   * 256 + chB * 16);
            mma_bf16(acc[0], a, b[0], b[1]);
            mma_bf16(acc[1], a, b[2], b[3]);
        }
        __syncthreads();
    }

    // gates: sigmoid -> smem
    {
        int row0 = wm + (lid >> 2);
        int row1 = row0 + 8;
        #pragma unroll
        for (int j = 0; j < 2; j++) {
            int n0 = nb + j * 8 + (lid & 3) * 2;
            sm.g[row0 * NT + n0]     = sigf(acc[j][0]);
            sm.g[row0 * NT + n0 + 1] = sigf(acc[j][1]);
            sm.g[row1 * NT + n0]     = sigf(acc[j][2]);
            sm.g[row1 * NT + n0 + 1] = sigf(acc[j][3]);
        }
    }
    __syncthreads();

    // gated reduction + scatter (tokens L2-hot; output written streaming)
    const int wsub = tid >> 6;
    const int h    = (tid >> 5) & 1;
    const int dq   = tid & 31;

    for (int p = 0; p < 8; p++) {
        int wl = p * 4 + wsub;
        int wg = w_base + wl;
        if (wg >= W) continue;
        const float* gp = sm.g + (wl * 2 + h) * NT;
        const int*   sp = sm.widx + wl * KWIN;
        float4 acc4 = make_float4(0.f, 0.f, 0.f, 0.f);
        #pragma unroll 8
        for (int k = 0; k < KWIN; k++) {
            float gk = gp[k];
            const float4 t4 = *reinterpret_cast<const float4*>(
                buffer + ((size_t)sp[k] * (NUM_HEADS * HEAD_DIM)
                          + h * HEAD_DIM + dq * 4));
            acc4.x += gk * t4.x;
            acc4.y += gk * t4.y;
            acc4.z += gk * t4.z;
            acc4.w += gk * t4.w;
        }
        __stcs(reinterpret_cast<float4*>(
                   out + ((size_t)sm.dst[wl] * (NUM_HEADS * HEAD_DIM)
                          + h * HEAD_DIM + dq * 4)),
               acc4);
    }
}

// ============================================================================
// Launch
// ============================================================================
extern "C" void kernel_launch(void* const* d_in, const int* in_sizes, int n_in,
                              void* d_out, int out_size)
{
    const float* buffer = (const float*)d_in[0];
    const float* cbuf   = (const float*)d_in[1];
    const float* gw     = (const float*)d_in[2];
    const int*   widx   = (const int*)d_in[3];
    const int*   dest   = (const int*)d_in[4];
    int W     = in_sizes[4];
    int crows = out_size / (NUM_HEADS * HEAD_DIM);

    cudaFuncSetAttribute(fused_kernel,
                         cudaFuncAttributeMaxDynamicSharedMemorySize, SMEM_BYTES);

    // single pre-kernel: gw -> bf16 + dest bitmap set
    prep_kernel<<<128, 256>>>(gw, dest, W);

    int Mtot = 2 * W;
    int nblk = (Mtot + MT - 1) / MT;          // GEMM blocks (0 allowed)
    fused_kernel<<<nblk + NCOPY, 256, SMEM_BYTES>>>(
        buffer, cbuf, widx, dest, (float*)d_out, W, Mtot, nblk, crows);
}